// round 2
// baseline (speedup 1.0000x reference)
#include <cuda_runtime.h>
#include <cstdint>

typedef unsigned long long ull;

// ---------- packed f32x2 helpers (FFMA2 path, sm_103a) ----------
__device__ __forceinline__ ull f2pack(float lo, float hi) {
    ull r; asm("mov.b64 %0,{%1,%2};" : "=l"(r) : "f"(lo), "f"(hi)); return r;
}
__device__ __forceinline__ void f2unpack(ull a, float& lo, float& hi) {
    asm("mov.b64 {%0,%1},%2;" : "=f"(lo), "=f"(hi) : "l"(a));
}
__device__ __forceinline__ ull f2mul(ull a, ull b) {
    ull r; asm("mul.rn.f32x2 %0,%1,%2;" : "=l"(r) : "l"(a), "l"(b)); return r;
}
__device__ __forceinline__ ull f2add(ull a, ull b) {
    ull r; asm("add.rn.f32x2 %0,%1,%2;" : "=l"(r) : "l"(a), "l"(b)); return r;
}
__device__ __forceinline__ ull f2fma(ull a, ull b, ull c) {
    ull r; asm("fma.rn.f32x2 %0,%1,%2,%3;" : "=l"(r) : "l"(a), "l"(b), "l"(c)); return r;
}

#define TILE     32
#define HALO     5
#define IN_DIM   42            // TILE + 2*HALO
#define IN_PITCH 44            // padded to even -> 16B-aligned ull2 loads
#define CELL     6             // hb cell stride (48B): conflict-free LDS.128
#define HB_ROW   (TILE * CELL) // 192 ull per hb row
#define NPIX     12582912.0    // 48 * 512 * 512
#define NBLOCKS  6144

__device__ double        g_acc  = 0.0;
__device__ unsigned int  g_done = 0u;

// smem (ull units): sp[42*44]=1848, st[42*44]=1848, hb[42*192]=8064
// total = 11760 ull = 94080 bytes; 2 CTAs/SM = 188160 < 228KB
__global__ __launch_bounds__(256, 2) void ssim_main_k(
    const float* __restrict__ pred,
    const float* __restrict__ targ,
    const float* __restrict__ win,
    float* __restrict__ out)
{
    extern __shared__ ull sm[];
    ull* sp = sm;
    ull* st = sm + 1848;
    ull* hb = sm + 3696;

    const int tid = threadIdx.x;

    // --- recover separable 1D window: w1[j] = win[55+j] / sum_j win[55+j] ---
    float rowsum = 0.f;
#pragma unroll
    for (int j = 0; j < 11; j++) rowsum += __ldg(win + 55 + j);
    const float invr = 1.0f / rowsum;
    ull ww[11];
#pragma unroll
    for (int j = 0; j < 11; j++) {
        float w = __ldg(win + 55 + j) * invr;
        ww[j] = f2pack(w, w);
    }

    const int ox = blockIdx.x * TILE;
    const int oy = blockIdx.y * TILE;
    const int pz = blockIdx.z;                  // plane pair 0..23
    const float* p0 = pred + (size_t)pz * 524288;
    const float* p1 = p0 + 262144;
    const float* t0 = targ + (size_t)pz * 524288;
    const float* t1 = t0 + 262144;

    // --- load 42x42 halo tile (zero pad outside image), pitch 44 ---
#pragma unroll
    for (int i = 0; i < 7; i++) {
        int idx = tid + i * 256;
        if (idx < 1764) {
            int r = idx / IN_DIM, c = idx - r * IN_DIM;
            int gy = oy + r - HALO, gx = ox + c - HALO;
            bool inb = ((unsigned)gy < 512u) && ((unsigned)gx < 512u);
            float a0 = 0.f, a1 = 0.f, b0 = 0.f, b1 = 0.f;
            if (inb) {
                int g = gy * 512 + gx;
                a0 = __ldg(p0 + g); a1 = __ldg(p1 + g);
                b0 = __ldg(t0 + g); b1 = __ldg(t1 + g);
            }
            sp[r * IN_PITCH + c] = f2pack(a0, a1);
            st[r * IN_PITCH + c] = f2pack(b0, b1);
        }
    }
    __syncthreads();

    // --- horizontal blur: 42 rows x 8 x-groups (4 outputs each) = 336 items ---
    for (int it = tid; it < 336; it += 256) {
        const int r  = it >> 3;
        const int x0 = (it & 7) * 4;
        ull acc[5][4];
#pragma unroll
        for (int s = 0; s < 5; s++)
#pragma unroll
            for (int j = 0; j < 4; j++) acc[s][j] = 0ULL;

        const ull* rp = sp + r * IN_PITCH + x0;   // 16B aligned (even index)
        const ull* rt = st + r * IN_PITCH + x0;
#pragma unroll
        for (int kk = 0; kk < 7; kk++) {
            ulonglong2 P = *reinterpret_cast<const ulonglong2*>(rp + 2 * kk);
            ulonglong2 T = *reinterpret_cast<const ulonglong2*>(rt + 2 * kk);
#pragma unroll
            for (int h = 0; h < 2; h++) {
                const int k = 2 * kk + h;
                ull p = h ? P.y : P.x;
                ull t = h ? T.y : T.x;
                ull pp = f2mul(p, p), tt = f2mul(t, t), pt = f2mul(p, t);
#pragma unroll
                for (int j = 0; j < 4; j++) {
                    const int ki = k - j;
                    if (ki >= 0 && ki <= 10) {
                        ull w = ww[ki];
                        acc[0][j] = f2fma(p,  w, acc[0][j]);
                        acc[1][j] = f2fma(t,  w, acc[1][j]);
                        acc[2][j] = f2fma(pp, w, acc[2][j]);
                        acc[3][j] = f2fma(tt, w, acc[3][j]);
                        acc[4][j] = f2fma(pt, w, acc[4][j]);
                    }
                }
            }
        }
        // store: cell (r, x0+j) = 6-ull slot, 16B aligned
#pragma unroll
        for (int j = 0; j < 4; j++) {
            ull* cell = hb + r * HB_ROW + (x0 + j) * CELL;
            *reinterpret_cast<ulonglong2*>(cell)     = make_ulonglong2(acc[0][j], acc[1][j]);
            *reinterpret_cast<ulonglong2*>(cell + 2) = make_ulonglong2(acc[2][j], acc[3][j]);
            cell[4] = acc[4][j];
        }
    }
    __syncthreads();

    // --- vertical blur + SSIM epilogue: column x, rows y0..y0+3 ---
    float lsum = 0.f;
    {
        const int x  = tid & 31;
        const int y0 = (tid >> 5) * 4;
        ull acc[5][4];
#pragma unroll
        for (int s = 0; s < 5; s++)
#pragma unroll
            for (int j = 0; j < 4; j++) acc[s][j] = 0ULL;

#pragma unroll
        for (int k = 0; k < 14; k++) {
            const ull* cell = hb + (y0 + k) * HB_ROW + x * CELL;
            ulonglong2 a01 = *reinterpret_cast<const ulonglong2*>(cell);
            ulonglong2 a23 = *reinterpret_cast<const ulonglong2*>(cell + 2);
            ulonglong2 a4x = *reinterpret_cast<const ulonglong2*>(cell + 4); // .y = pad
            ull v0 = a01.x, v1 = a01.y, v2 = a23.x, v3 = a23.y, v4 = a4x.x;
#pragma unroll
            for (int j = 0; j < 4; j++) {
                const int ki = k - j;
                if (ki >= 0 && ki <= 10) {
                    ull w = ww[ki];
                    acc[0][j] = f2fma(v0, w, acc[0][j]);
                    acc[1][j] = f2fma(v1, w, acc[1][j]);
                    acc[2][j] = f2fma(v2, w, acc[2][j]);
                    acc[3][j] = f2fma(v3, w, acc[3][j]);
                    acc[4][j] = f2fma(v4, w, acc[4][j]);
                }
            }
        }

        const ull TWO  = f2pack(2.0f, 2.0f);
        const ull C1p  = f2pack(1e-4f, 1e-4f);
        const ull C2p  = f2pack(9e-4f, 9e-4f);
        const ull EPSp = f2pack(1e-8f, 1e-8f);
        const ull SGN  = 0x8000000080000000ULL;

#pragma unroll
        for (int j = 0; j < 4; j++) {
            ull mu1 = acc[0][j], mu2 = acc[1][j];
            ull bpp = acc[2][j], btt = acc[3][j], bpt = acc[4][j];
            ull nmu1 = mu1 ^ SGN;
            ull nmu2 = mu2 ^ SGN;
            ull mu1mu2 = f2mul(mu1, mu2);
            ull mu1sq  = f2mul(mu1, mu1);
            ull mu2sq  = f2mul(mu2, mu2);
            ull sig1   = f2fma(nmu1, mu1, bpp);
            ull sig2   = f2fma(nmu2, mu2, btt);
            ull sig12  = f2fma(nmu1, mu2, bpt);
            ull num1 = f2fma(mu1mu2, TWO, C1p);
            ull num2 = f2fma(sig12,  TWO, C2p);
            ull den1 = f2add(f2add(mu1sq, mu2sq), C1p);
            ull den2 = f2add(f2add(sig1, sig2), C2p);
            ull num  = f2mul(num1, num2);
            ull den  = f2fma(den1, den2, EPSp);
            float n0, n1, d0, d1;
            f2unpack(num, n0, n1);
            f2unpack(den, d0, d1);
            lsum += __fdividef(n0, d0) + __fdividef(n1, d1);
        }
    }

    // --- block reduction -> double atomic ---
#pragma unroll
    for (int o = 16; o; o >>= 1) lsum += __shfl_xor_sync(0xffffffffu, lsum, o);
    __shared__ float warp_part[8];
    if ((tid & 31) == 0) warp_part[tid >> 5] = lsum;
    __syncthreads();
    if (tid < 32) {
        float v = (tid < 8) ? warp_part[tid] : 0.f;
#pragma unroll
        for (int o = 4; o; o >>= 1) v += __shfl_xor_sync(0xffffffffu, v, o);
        if (tid == 0) atomicAdd(&g_acc, (double)v);
    }

    // --- last-block finalize (self-resetting for graph replay) ---
    if (tid == 0) {
        __threadfence();
        unsigned int old = atomicAdd(&g_done, 1u);
        if (old == NBLOCKS - 1u) {
            __threadfence();
            double total = *((volatile double*)&g_acc);
            out[0] = 1.0f - (float)(total * (1.0 / NPIX));
            g_acc  = 0.0;
            g_done = 0u;
        }
    }
}

extern "C" void kernel_launch(void* const* d_in, const int* in_sizes, int n_in,
                              void* d_out, int out_size)
{
    const float* pred = (const float*)d_in[0];
    const float* targ = (const float*)d_in[1];
    const float* win  = (const float*)d_in[2];
    float* out = (float*)d_out;

    const int smem_bytes = 94080;
    cudaFuncSetAttribute(ssim_main_k, cudaFuncAttributeMaxDynamicSharedMemorySize, smem_bytes);

    dim3 grid(16, 16, 24), blk(256);
    ssim_main_k<<<grid, blk, smem_bytes>>>(pred, targ, win, out);
}

// round 3
// speedup vs baseline: 1.1925x; 1.1925x over previous
#include <cuda_runtime.h>
#include <cstdint>

typedef unsigned long long ull;

// ---------- packed f32x2 helpers ----------
__device__ __forceinline__ ull f2pack(float lo, float hi) {
    ull r; asm("mov.b64 %0,{%1,%2};" : "=l"(r) : "f"(lo), "f"(hi)); return r;
}
__device__ __forceinline__ void f2unpack(ull a, float& lo, float& hi) {
    asm("mov.b64 {%0,%1},%2;" : "=f"(lo), "=f"(hi) : "l"(a));
}
__device__ __forceinline__ ull f2mul(ull a, ull b) {
    ull r; asm("mul.rn.f32x2 %0,%1,%2;" : "=l"(r) : "l"(a), "l"(b)); return r;
}
__device__ __forceinline__ ull f2add(ull a, ull b) {
    ull r; asm("add.rn.f32x2 %0,%1,%2;" : "=l"(r) : "l"(a), "l"(b)); return r;
}
__device__ __forceinline__ ull f2fma(ull a, ull b, ull c) {
    ull r; asm("fma.rn.f32x2 %0,%1,%2,%3;" : "=l"(r) : "l"(a), "l"(b), "l"(c)); return r;
}

#define TILE     32
#define HALO     5
#define IN_DIM   42              // TILE + 2*HALO
#define SP_PITCH 49              // 98 words; 98 mod 32 = 2 -> conflict-free lane-stride
#define SP_SIZE  (IN_DIM * SP_PITCH)   // 2058 ull
#define HB_PITCH 33              // 66 words; 66 mod 32 = 2 -> conflict-free h-stores
#define HB_SIG   (IN_DIM * HB_PITCH)   // 1386 ull per signal
#define NPIX     12582912.0      // 48 * 512 * 512
#define NBLOCKS  6144

__device__ double        g_acc  = 0.0;
__device__ unsigned int  g_done = 0u;

// smem (ull): sp[2058], st[2058], hb[5*1386=6930]  -> 11046 ull = 88368 B
// 2 CTAs/SM = 176.7 KB < 228 KB
__global__ __launch_bounds__(128) void ssim_main_k(
    const float* __restrict__ pred,
    const float* __restrict__ targ,
    const float* __restrict__ win,
    float* __restrict__ out)
{
    extern __shared__ ull sm[];
    ull* sp = sm;
    ull* st = sm + SP_SIZE;
    ull* hb = sm + 2 * SP_SIZE;

    const int tid  = threadIdx.x;
    const int lane = tid & 31;
    const int warp = tid >> 5;

    // --- recover separable 1D window: w1[j] = win[55+j] / sum_j win[55+j] ---
    float rowsum = 0.f;
#pragma unroll
    for (int j = 0; j < 11; j++) rowsum += __ldg(win + 55 + j);
    const float invr = 1.0f / rowsum;
    ull ww[11];
#pragma unroll
    for (int j = 0; j < 11; j++) {
        float w = __ldg(win + 55 + j) * invr;
        ww[j] = f2pack(w, w);
    }

    const int ox = blockIdx.x * TILE;
    const int oy = blockIdx.y * TILE;
    const int pz = blockIdx.z;                  // plane pair 0..23
    const float* p0 = pred + (size_t)pz * 524288;
    const float* p1 = p0 + 262144;
    const float* t0 = targ + (size_t)pz * 524288;
    const float* t1 = t0 + 262144;

    // --- load 42x42 halo tile (zero pad), pitch 49 ---
#pragma unroll
    for (int i = 0; i < 14; i++) {
        int idx = tid + i * 128;
        if (idx < 1764) {
            int r = idx / IN_DIM, c = idx - r * IN_DIM;
            int gy = oy + r - HALO, gx = ox + c - HALO;
            bool inb = ((unsigned)gy < 512u) && ((unsigned)gx < 512u);
            float a0 = 0.f, a1 = 0.f, b0 = 0.f, b1 = 0.f;
            if (inb) {
                int g = gy * 512 + gx;
                a0 = __ldg(p0 + g); a1 = __ldg(p1 + g);
                b0 = __ldg(t0 + g); b1 = __ldg(t1 + g);
            }
            sp[r * SP_PITCH + c] = f2pack(a0, a1);
            st[r * SP_PITCH + c] = f2pack(b0, b1);
        }
    }
    __syncthreads();

    // --- horizontal blur: lane = row, warp picks x-group; sliding 4-out window ---
    // warp w handles x0 = 4*w and x0 = 4*w + 16 (8 groups total across 4 warps)
#pragma unroll
    for (int ri = 0; ri < 2; ri++) {
        const int r = ri * 32 + lane;
        if (r < IN_DIM) {
            const ull* rp = sp + r * SP_PITCH;
            const ull* rt = st + r * SP_PITCH;
#pragma unroll
            for (int g = 0; g < 2; g++) {
                const int x0 = warp * 4 + g * 16;
                ull acc[5][4];
#pragma unroll
                for (int s = 0; s < 5; s++)
#pragma unroll
                    for (int j = 0; j < 4; j++) acc[s][j] = 0ULL;
#pragma unroll
                for (int k = 0; k < 14; k++) {
                    ull p = rp[x0 + k];
                    ull t = rt[x0 + k];
                    ull pp = f2mul(p, p), tt = f2mul(t, t), pt = f2mul(p, t);
#pragma unroll
                    for (int j = 0; j < 4; j++) {
                        const int ki = k - j;
                        if (ki >= 0 && ki <= 10) {
                            ull w = ww[ki];
                            acc[0][j] = f2fma(p,  w, acc[0][j]);
                            acc[1][j] = f2fma(t,  w, acc[1][j]);
                            acc[2][j] = f2fma(pp, w, acc[2][j]);
                            acc[3][j] = f2fma(tt, w, acc[3][j]);
                            acc[4][j] = f2fma(pt, w, acc[4][j]);
                        }
                    }
                }
#pragma unroll
                for (int s = 0; s < 5; s++)
#pragma unroll
                    for (int j = 0; j < 4; j++)
                        hb[s * HB_SIG + r * HB_PITCH + x0 + j] = acc[s][j];
            }
        }
    }
    __syncthreads();

    // --- vertical blur + epilogue: x = lane, 8 y-outputs per thread, 3 passes ---
    float lsum = 0.f;
    {
        const int x  = lane;
        const int y0 = warp * 8;                 // outputs y0..y0+7, rows y0..y0+17

        const ull TWO  = f2pack(2.0f, 2.0f);
        const ull C1p  = f2pack(1e-4f, 1e-4f);
        const ull C2p  = f2pack(9e-4f, 9e-4f);
        const ull C12p = f2pack(1e-4f + 9e-4f, 1e-4f + 9e-4f);
        const ull EPSp = f2pack(1e-8f, 1e-8f);
        const ull SGN  = 0x8000000080000000ULL;

        ull m12[8], den1[8], den2[8];

        // pass A: mu1, mu2
        {
            ull a0[8], a1[8];
#pragma unroll
            for (int j = 0; j < 8; j++) { a0[j] = 0ULL; a1[j] = 0ULL; }
            const ull* h0 = hb + 0 * HB_SIG + y0 * HB_PITCH + x;
            const ull* h1 = hb + 1 * HB_SIG + y0 * HB_PITCH + x;
#pragma unroll
            for (int k = 0; k < 18; k++) {
                ull v0 = h0[k * HB_PITCH];
                ull v1 = h1[k * HB_PITCH];
#pragma unroll
                for (int j = 0; j < 8; j++) {
                    const int ki = k - j;
                    if (ki >= 0 && ki <= 10) {
                        ull w = ww[ki];
                        a0[j] = f2fma(v0, w, a0[j]);
                        a1[j] = f2fma(v1, w, a1[j]);
                    }
                }
            }
#pragma unroll
            for (int j = 0; j < 8; j++) {
                ull mu1 = a0[j], mu2 = a1[j];
                m12[j]  = f2mul(mu1, mu2);
                den1[j] = f2fma(mu1, mu1, f2fma(mu2, mu2, C1p));  // mu1^2+mu2^2+C1
            }
        }

        // pass B: pp, tt  ->  den2 = (bpp+btt) - den1 + (C1+C2)
        {
            ull a2[8], a3[8];
#pragma unroll
            for (int j = 0; j < 8; j++) { a2[j] = 0ULL; a3[j] = 0ULL; }
            const ull* h2 = hb + 2 * HB_SIG + y0 * HB_PITCH + x;
            const ull* h3 = hb + 3 * HB_SIG + y0 * HB_PITCH + x;
#pragma unroll
            for (int k = 0; k < 18; k++) {
                ull v2 = h2[k * HB_PITCH];
                ull v3 = h3[k * HB_PITCH];
#pragma unroll
                for (int j = 0; j < 8; j++) {
                    const int ki = k - j;
                    if (ki >= 0 && ki <= 10) {
                        ull w = ww[ki];
                        a2[j] = f2fma(v2, w, a2[j]);
                        a3[j] = f2fma(v3, w, a3[j]);
                    }
                }
            }
#pragma unroll
            for (int j = 0; j < 8; j++) {
                ull s = f2add(a2[j], a3[j]);
                den2[j] = f2add(f2add(s, C12p), den1[j] ^ SGN);   // s - den1 + C1 + C2
            }
        }

        // pass C: pt -> epilogue
        {
            ull a4[8];
#pragma unroll
            for (int j = 0; j < 8; j++) a4[j] = 0ULL;
            const ull* h4 = hb + 4 * HB_SIG + y0 * HB_PITCH + x;
#pragma unroll
            for (int k = 0; k < 18; k++) {
                ull v4 = h4[k * HB_PITCH];
#pragma unroll
                for (int j = 0; j < 8; j++) {
                    const int ki = k - j;
                    if (ki >= 0 && ki <= 10)
                        a4[j] = f2fma(v4, ww[ki], a4[j]);
                }
            }
#pragma unroll
            for (int j = 0; j < 8; j++) {
                ull sig12 = f2add(a4[j], m12[j] ^ SGN);           // bpt - mu1mu2
                ull num1  = f2fma(m12[j], TWO, C1p);              // 2*m12 + C1
                ull num2  = f2fma(sig12,  TWO, C2p);              // 2*sig12 + C2
                ull num   = f2mul(num1, num2);
                ull den   = f2fma(den1[j], den2[j], EPSp);
                float n0, n1, d0, d1;
                f2unpack(num, n0, n1);
                f2unpack(den, d0, d1);
                lsum += __fdividef(n0, d0) + __fdividef(n1, d1);
            }
        }
    }

    // --- block reduction -> double atomic ---
#pragma unroll
    for (int o = 16; o; o >>= 1) lsum += __shfl_xor_sync(0xffffffffu, lsum, o);
    __shared__ float warp_part[4];
    if (lane == 0) warp_part[warp] = lsum;
    __syncthreads();
    if (tid == 0) {
        float v = warp_part[0] + warp_part[1] + warp_part[2] + warp_part[3];
        atomicAdd(&g_acc, (double)v);
        __threadfence();
        unsigned int old = atomicAdd(&g_done, 1u);
        if (old == NBLOCKS - 1u) {
            __threadfence();
            double total = *((volatile double*)&g_acc);
            out[0] = 1.0f - (float)(total * (1.0 / NPIX));
            g_acc  = 0.0;
            g_done = 0u;
        }
    }
}

extern "C" void kernel_launch(void* const* d_in, const int* in_sizes, int n_in,
                              void* d_out, int out_size)
{
    const float* pred = (const float*)d_in[0];
    const float* targ = (const float*)d_in[1];
    const float* win  = (const float*)d_in[2];
    float* out = (float*)d_out;

    const int smem_bytes = 88368;
    cudaFuncSetAttribute(ssim_main_k, cudaFuncAttributeMaxDynamicSharedMemorySize, smem_bytes);

    dim3 grid(16, 16, 24), blk(128);
    ssim_main_k<<<grid, blk, smem_bytes>>>(pred, targ, win, out);
}

// round 4
// speedup vs baseline: 1.3245x; 1.1107x over previous
#include <cuda_runtime.h>
#include <cstdint>

typedef unsigned long long ull;

// ---------- packed f32x2 helpers ----------
__device__ __forceinline__ ull f2pack(float lo, float hi) {
    ull r; asm("mov.b64 %0,{%1,%2};" : "=l"(r) : "f"(lo), "f"(hi)); return r;
}
__device__ __forceinline__ void f2unpack(ull a, float& lo, float& hi) {
    asm("mov.b64 {%0,%1},%2;" : "=f"(lo), "=f"(hi) : "l"(a));
}
__device__ __forceinline__ ull f2mul(ull a, ull b) {
    ull r; asm("mul.rn.f32x2 %0,%1,%2;" : "=l"(r) : "l"(a), "l"(b)); return r;
}
__device__ __forceinline__ ull f2add(ull a, ull b) {
    ull r; asm("add.rn.f32x2 %0,%1,%2;" : "=l"(r) : "l"(a), "l"(b)); return r;
}
__device__ __forceinline__ ull f2fma(ull a, ull b, ull c) {
    ull r; asm("fma.rn.f32x2 %0,%1,%2,%3;" : "=l"(r) : "l"(a), "l"(b), "l"(c)); return r;
}

#define TILE     32
#define HALO     5
#define IN_DIM   42                    // TILE + 2*HALO
#define SP_PITCH 43                    // 86 words; 2*(11 mod 16) pattern -> conflict-free
#define SP_SIZE  (IN_DIM * SP_PITCH)   // 1806 ull
#define HB_PITCH 33                    // 66 mod 32 = 2 -> conflict-free
#define HB_SIG   (IN_DIM * HB_PITCH)   // 1386 ull per signal
#define NSIG     4                     // mu1, mu2, (pp+tt), pt
#define NPIX     12582912.0            // 48 * 512 * 512
#define NBLOCKS  6144

__device__ double        g_acc  = 0.0;
__device__ unsigned int  g_done = 0u;

// smem (ull): sp[1806], st[1806], hb[4*1386=5544] -> 9156 ull = 73248 B
// 3 CTAs/SM = 219.7 KB <= 228 KB
__global__ __launch_bounds__(256, 3) void ssim_main_k(
    const float* __restrict__ pred,
    const float* __restrict__ targ,
    const float* __restrict__ win,
    float* __restrict__ out)
{
    extern __shared__ ull sm[];
    ull* sp = sm;
    ull* st = sm + SP_SIZE;
    ull* hb = sm + 2 * SP_SIZE;

    const int tid  = threadIdx.x;
    const int lane = tid & 31;
    const int warp = tid >> 5;

    // --- recover separable 1D window: w1[j] = win[55+j] / sum_j win[55+j] ---
    float rowsum = 0.f;
#pragma unroll
    for (int j = 0; j < 11; j++) rowsum += __ldg(win + 55 + j);
    const float invr = 1.0f / rowsum;
    ull ww[11];
#pragma unroll
    for (int j = 0; j < 11; j++) {
        float w = __ldg(win + 55 + j) * invr;
        ww[j] = f2pack(w, w);
    }

    const int ox = blockIdx.x * TILE;
    const int oy = blockIdx.y * TILE;
    const int pz = blockIdx.z;                  // plane pair 0..23
    const float* p0 = pred + (size_t)pz * 524288;
    const float* p1 = p0 + 262144;
    const float* t0 = targ + (size_t)pz * 524288;
    const float* t1 = t0 + 262144;

    // --- load 42x42 halo tile (zero pad), pitch 43 ---
#pragma unroll
    for (int i = 0; i < 7; i++) {
        int idx = tid + i * 256;
        if (idx < 1764) {
            int r = idx / IN_DIM, c = idx - r * IN_DIM;
            int gy = oy + r - HALO, gx = ox + c - HALO;
            bool inb = ((unsigned)gy < 512u) && ((unsigned)gx < 512u);
            float a0 = 0.f, a1 = 0.f, b0 = 0.f, b1 = 0.f;
            if (inb) {
                int g = gy * 512 + gx;
                a0 = __ldg(p0 + g); a1 = __ldg(p1 + g);
                b0 = __ldg(t0 + g); b1 = __ldg(t1 + g);
            }
            sp[r * SP_PITCH + c] = f2pack(a0, a1);
            st[r * SP_PITCH + c] = f2pack(b0, b1);
        }
    }
    __syncthreads();

    // --- horizontal blur: lane = row, warp = x-group (8 warps x 4 outputs = 32) ---
    {
        const int x0 = warp * 4;
#pragma unroll
        for (int ri = 0; ri < 2; ri++) {
            const int r = ri * 32 + lane;
            if (r < IN_DIM) {
                const ull* rp = sp + r * SP_PITCH + x0;
                const ull* rt = st + r * SP_PITCH + x0;
                ull acc[NSIG][4];
#pragma unroll
                for (int s = 0; s < NSIG; s++)
#pragma unroll
                    for (int j = 0; j < 4; j++) acc[s][j] = 0ULL;
#pragma unroll
                for (int k = 0; k < 14; k++) {
                    ull p = rp[k];
                    ull t = rt[k];
                    ull sq = f2fma(p, p, f2mul(t, t));   // p^2 + t^2
                    ull pt = f2mul(p, t);
#pragma unroll
                    for (int j = 0; j < 4; j++) {
                        const int ki = k - j;
                        if (ki >= 0 && ki <= 10) {
                            ull w = ww[ki];
                            acc[0][j] = f2fma(p,  w, acc[0][j]);
                            acc[1][j] = f2fma(t,  w, acc[1][j]);
                            acc[2][j] = f2fma(sq, w, acc[2][j]);
                            acc[3][j] = f2fma(pt, w, acc[3][j]);
                        }
                    }
                }
#pragma unroll
                for (int s = 0; s < NSIG; s++)
#pragma unroll
                    for (int j = 0; j < 4; j++)
                        hb[s * HB_SIG + r * HB_PITCH + x0 + j] = acc[s][j];
            }
        }
    }
    __syncthreads();

    // --- vertical blur + epilogue: x = lane, y0 = warp*4, 3 passes ---
    float lsum = 0.f;
    {
        const int y0 = warp * 4;

        const ull TWO  = f2pack(2.0f, 2.0f);
        const ull C1p  = f2pack(1e-4f, 1e-4f);
        const ull C2p  = f2pack(9e-4f, 9e-4f);
        const ull C12p = f2pack(1e-4f + 9e-4f, 1e-4f + 9e-4f);
        const ull EPSp = f2pack(1e-8f, 1e-8f);
        const ull SGN  = 0x8000000080000000ULL;

        ull m12[4], den1[4], den2[4];

        // pass A: mu1, mu2
        {
            ull a0[4], a1[4];
#pragma unroll
            for (int j = 0; j < 4; j++) { a0[j] = 0ULL; a1[j] = 0ULL; }
            const ull* h0 = hb + 0 * HB_SIG + y0 * HB_PITCH + lane;
            const ull* h1 = hb + 1 * HB_SIG + y0 * HB_PITCH + lane;
#pragma unroll
            for (int k = 0; k < 14; k++) {
                ull v0 = h0[k * HB_PITCH];
                ull v1 = h1[k * HB_PITCH];
#pragma unroll
                for (int j = 0; j < 4; j++) {
                    const int ki = k - j;
                    if (ki >= 0 && ki <= 10) {
                        ull w = ww[ki];
                        a0[j] = f2fma(v0, w, a0[j]);
                        a1[j] = f2fma(v1, w, a1[j]);
                    }
                }
            }
#pragma unroll
            for (int j = 0; j < 4; j++) {
                ull mu1 = a0[j], mu2 = a1[j];
                m12[j]  = f2mul(mu1, mu2);
                den1[j] = f2fma(mu1, mu1, f2fma(mu2, mu2, C1p));  // mu1^2+mu2^2+C1
            }
        }

        // pass B: blur(pp+tt) -> den2 = bsq - den1 + (C1+C2)
        {
            ull a2[4];
#pragma unroll
            for (int j = 0; j < 4; j++) a2[j] = 0ULL;
            const ull* h2 = hb + 2 * HB_SIG + y0 * HB_PITCH + lane;
#pragma unroll
            for (int k = 0; k < 14; k++) {
                ull v2 = h2[k * HB_PITCH];
#pragma unroll
                for (int j = 0; j < 4; j++) {
                    const int ki = k - j;
                    if (ki >= 0 && ki <= 10)
                        a2[j] = f2fma(v2, ww[ki], a2[j]);
                }
            }
#pragma unroll
            for (int j = 0; j < 4; j++)
                den2[j] = f2add(f2add(a2[j], C12p), den1[j] ^ SGN);
        }

        // pass C: blur(pt) -> epilogue
        {
            ull a3[4];
#pragma unroll
            for (int j = 0; j < 4; j++) a3[j] = 0ULL;
            const ull* h3 = hb + 3 * HB_SIG + y0 * HB_PITCH + lane;
#pragma unroll
            for (int k = 0; k < 14; k++) {
                ull v3 = h3[k * HB_PITCH];
#pragma unroll
                for (int j = 0; j < 4; j++) {
                    const int ki = k - j;
                    if (ki >= 0 && ki <= 10)
                        a3[j] = f2fma(v3, ww[ki], a3[j]);
                }
            }
#pragma unroll
            for (int j = 0; j < 4; j++) {
                ull sig12 = f2add(a3[j], m12[j] ^ SGN);   // bpt - mu1mu2
                ull num1  = f2fma(m12[j], TWO, C1p);
                ull num2  = f2fma(sig12,  TWO, C2p);
                ull num   = f2mul(num1, num2);
                ull den   = f2fma(den1[j], den2[j], EPSp);
                float n0, n1, d0, d1;
                f2unpack(num, n0, n1);
                f2unpack(den, d0, d1);
                lsum += __fdividef(n0, d0) + __fdividef(n1, d1);
            }
        }
    }

    // --- block reduction -> double atomic + last-block finalize ---
#pragma unroll
    for (int o = 16; o; o >>= 1) lsum += __shfl_xor_sync(0xffffffffu, lsum, o);
    __shared__ float warp_part[8];
    if (lane == 0) warp_part[warp] = lsum;
    __syncthreads();
    if (tid == 0) {
        float v = 0.f;
#pragma unroll
        for (int i = 0; i < 8; i++) v += warp_part[i];
        atomicAdd(&g_acc, (double)v);
        __threadfence();
        unsigned int old = atomicAdd(&g_done, 1u);
        if (old == NBLOCKS - 1u) {
            __threadfence();
            double total = *((volatile double*)&g_acc);
            out[0] = 1.0f - (float)(total * (1.0 / NPIX));
            g_acc  = 0.0;
            g_done = 0u;
        }
    }
}

extern "C" void kernel_launch(void* const* d_in, const int* in_sizes, int n_in,
                              void* d_out, int out_size)
{
    const float* pred = (const float*)d_in[0];
    const float* targ = (const float*)d_in[1];
    const float* win  = (const float*)d_in[2];
    float* out = (float*)d_out;

    const int smem_bytes = 73248;
    cudaFuncSetAttribute(ssim_main_k, cudaFuncAttributeMaxDynamicSharedMemorySize, smem_bytes);

    dim3 grid(16, 16, 24), blk(256);
    ssim_main_k<<<grid, blk, smem_bytes>>>(pred, targ, win, out);
}

// round 5
// speedup vs baseline: 1.4109x; 1.0652x over previous
#include <cuda_runtime.h>
#include <cstdint>

typedef unsigned long long ull;

// ---------- packed f32x2 helpers ----------
__device__ __forceinline__ ull f2pack(float lo, float hi) {
    ull r; asm("mov.b64 %0,{%1,%2};" : "=l"(r) : "f"(lo), "f"(hi)); return r;
}
__device__ __forceinline__ void f2unpack(ull a, float& lo, float& hi) {
    asm("mov.b64 {%0,%1},%2;" : "=f"(lo), "=f"(hi) : "l"(a));
}
__device__ __forceinline__ ull f2mul(ull a, ull b) {
    ull r; asm("mul.rn.f32x2 %0,%1,%2;" : "=l"(r) : "l"(a), "l"(b)); return r;
}
__device__ __forceinline__ ull f2add(ull a, ull b) {
    ull r; asm("add.rn.f32x2 %0,%1,%2;" : "=l"(r) : "l"(a), "l"(b)); return r;
}
__device__ __forceinline__ ull f2fma(ull a, ull b, ull c) {
    ull r; asm("fma.rn.f32x2 %0,%1,%2,%3;" : "=l"(r) : "l"(a), "l"(b), "l"(c)); return r;
}

#define TILE_W   32
#define TILE_H   22
#define HALO     5
#define IN_ROWS  32                    // TILE_H + 10 == one full warp of rows
#define IN_W     42                    // TILE_W + 10
#define SP_PITCH 43                    // 86 words mod 32 = 22 -> conflict-free lane-stride
#define SP_SIZE  (IN_ROWS * SP_PITCH)  // 1376 ull
#define HB_PITCH 33                    // 66 mod 32 = 2 -> conflict-free
#define HB_SIG   (IN_ROWS * HB_PITCH)  // 1056 ull per signal
#define NSIG     4                     // mu1, mu2, (pp+tt), pt
#define NPIX     12582912.0            // 48 * 512 * 512
#define NBLOCKS  9216                  // 16 x 24 x 24

__device__ double        g_acc  = 0.0;
__device__ unsigned int  g_done = 0u;

// ---- templated vertical pass: NO outputs starting at row y0 ----
template<int NO>
__device__ __forceinline__ float v_pass(const ull* __restrict__ hb,
                                        const ull ww[11], int lane, int y0, int gy0)
{
    const ull TWO  = f2pack(2.0f, 2.0f);
    const ull C1p  = f2pack(1e-4f, 1e-4f);
    const ull C2p  = f2pack(9e-4f, 9e-4f);
    const ull C12p = f2pack(1e-4f + 9e-4f, 1e-4f + 9e-4f);
    const ull EPSp = f2pack(1e-8f, 1e-8f);
    const ull SGN  = 0x8000000080000000ULL;

    ull m12[NO], den1[NO], den2[NO];
    float lsum = 0.f;

    // pass A: mu1, mu2
    {
        ull a0[NO], a1[NO];
#pragma unroll
        for (int j = 0; j < NO; j++) { a0[j] = 0ULL; a1[j] = 0ULL; }
        const ull* h0 = hb + 0 * HB_SIG + y0 * HB_PITCH + lane;
        const ull* h1 = hb + 1 * HB_SIG + y0 * HB_PITCH + lane;
#pragma unroll
        for (int k = 0; k < NO + 10; k++) {
            ull v0 = h0[k * HB_PITCH];
            ull v1 = h1[k * HB_PITCH];
#pragma unroll
            for (int j = 0; j < NO; j++) {
                const int ki = k - j;
                if (ki >= 0 && ki <= 10) {
                    ull w = ww[ki];
                    a0[j] = f2fma(v0, w, a0[j]);
                    a1[j] = f2fma(v1, w, a1[j]);
                }
            }
        }
#pragma unroll
        for (int j = 0; j < NO; j++) {
            ull mu1 = a0[j], mu2 = a1[j];
            m12[j]  = f2mul(mu1, mu2);
            den1[j] = f2fma(mu1, mu1, f2fma(mu2, mu2, C1p));   // mu1^2+mu2^2+C1
        }
    }

    // pass B: blur(pp+tt) -> den2 = bsq - den1 + (C1+C2)
    {
        ull a2[NO];
#pragma unroll
        for (int j = 0; j < NO; j++) a2[j] = 0ULL;
        const ull* h2 = hb + 2 * HB_SIG + y0 * HB_PITCH + lane;
#pragma unroll
        for (int k = 0; k < NO + 10; k++) {
            ull v2 = h2[k * HB_PITCH];
#pragma unroll
            for (int j = 0; j < NO; j++) {
                const int ki = k - j;
                if (ki >= 0 && ki <= 10)
                    a2[j] = f2fma(v2, ww[ki], a2[j]);
            }
        }
#pragma unroll
        for (int j = 0; j < NO; j++)
            den2[j] = f2add(f2add(a2[j], C12p), den1[j] ^ SGN);
    }

    // pass C: blur(pt) -> epilogue
    {
        ull a3[NO];
#pragma unroll
        for (int j = 0; j < NO; j++) a3[j] = 0ULL;
        const ull* h3 = hb + 3 * HB_SIG + y0 * HB_PITCH + lane;
#pragma unroll
        for (int k = 0; k < NO + 10; k++) {
            ull v3 = h3[k * HB_PITCH];
#pragma unroll
            for (int j = 0; j < NO; j++) {
                const int ki = k - j;
                if (ki >= 0 && ki <= 10)
                    a3[j] = f2fma(v3, ww[ki], a3[j]);
            }
        }
#pragma unroll
        for (int j = 0; j < NO; j++) {
            if (gy0 + j < 512) {
                ull sig12 = f2add(a3[j], m12[j] ^ SGN);   // bpt - mu1mu2
                ull num1  = f2fma(m12[j], TWO, C1p);
                ull num2  = f2fma(sig12,  TWO, C2p);
                ull num   = f2mul(num1, num2);
                ull den   = f2fma(den1[j], den2[j], EPSp);
                float n0, n1, d0, d1;
                f2unpack(num, n0, n1);
                f2unpack(den, d0, d1);
                lsum += __fdividef(n0, d0) + __fdividef(n1, d1);
            }
        }
    }
    return lsum;
}

// smem (ull): sp[1376], st[1376], hb[4*1056=4224] -> 6976 ull = 55808 B
// 4 CTAs/SM = 223.2 KB
__global__ __launch_bounds__(256, 4) void ssim_main_k(
    const float* __restrict__ pred,
    const float* __restrict__ targ,
    const float* __restrict__ win,
    float* __restrict__ out)
{
    extern __shared__ ull sm[];
    ull* sp = sm;
    ull* st = sm + SP_SIZE;
    ull* hb = sm + 2 * SP_SIZE;

    const int tid  = threadIdx.x;
    const int lane = tid & 31;
    const int warp = tid >> 5;

    // --- recover separable 1D window: w1[j] = win[55+j] / sum_j win[55+j] ---
    float rowsum = 0.f;
#pragma unroll
    for (int j = 0; j < 11; j++) rowsum += __ldg(win + 55 + j);
    const float invr = 1.0f / rowsum;
    ull ww[11];
#pragma unroll
    for (int j = 0; j < 11; j++) {
        float w = __ldg(win + 55 + j) * invr;
        ww[j] = f2pack(w, w);
    }

    const int ox = blockIdx.x * TILE_W;
    const int oy = blockIdx.y * TILE_H;
    const int pz = blockIdx.z;                  // plane pair 0..23
    const float* p0 = pred + (size_t)pz * 524288;
    const float* p1 = p0 + 262144;
    const float* t0 = targ + (size_t)pz * 524288;
    const float* t1 = t0 + 262144;

    // --- load 32x42 halo tile (zero pad), pitch 43 ---
#pragma unroll
    for (int i = 0; i < 6; i++) {
        int idx = tid + i * 256;
        if (idx < IN_ROWS * IN_W) {
            int r = idx / IN_W, c = idx - r * IN_W;
            int gy = oy + r - HALO, gx = ox + c - HALO;
            bool inb = ((unsigned)gy < 512u) && ((unsigned)gx < 512u);
            float a0 = 0.f, a1 = 0.f, b0 = 0.f, b1 = 0.f;
            if (inb) {
                int g = gy * 512 + gx;
                a0 = __ldg(p0 + g); a1 = __ldg(p1 + g);
                b0 = __ldg(t0 + g); b1 = __ldg(t1 + g);
            }
            sp[r * SP_PITCH + c] = f2pack(a0, a1);
            st[r * SP_PITCH + c] = f2pack(b0, b1);
        }
    }
    __syncthreads();

    // --- horizontal blur: lane = row (exactly 32), warp = x-group; 1 iteration ---
    {
        const int r  = lane;
        const int x0 = warp * 4;
        const ull* rp = sp + r * SP_PITCH + x0;
        const ull* rt = st + r * SP_PITCH + x0;
        ull acc[NSIG][4];
#pragma unroll
        for (int s = 0; s < NSIG; s++)
#pragma unroll
            for (int j = 0; j < 4; j++) acc[s][j] = 0ULL;
#pragma unroll
        for (int k = 0; k < 14; k++) {
            ull p = rp[k];
            ull t = rt[k];
            ull sq = f2fma(p, p, f2mul(t, t));   // p^2 + t^2
            ull pt = f2mul(p, t);
#pragma unroll
            for (int j = 0; j < 4; j++) {
                const int ki = k - j;
                if (ki >= 0 && ki <= 10) {
                    ull w = ww[ki];
                    acc[0][j] = f2fma(p,  w, acc[0][j]);
                    acc[1][j] = f2fma(t,  w, acc[1][j]);
                    acc[2][j] = f2fma(sq, w, acc[2][j]);
                    acc[3][j] = f2fma(pt, w, acc[3][j]);
                }
            }
        }
#pragma unroll
        for (int s = 0; s < NSIG; s++)
#pragma unroll
            for (int j = 0; j < 4; j++)
                hb[s * HB_SIG + r * HB_PITCH + x0 + j] = acc[s][j];
    }
    __syncthreads();

    // --- vertical blur + epilogue: x = lane; warps 0..5 -> 3 rows, 6..7 -> 2 ---
    float lsum;
    if (warp < 6) {
        const int y0 = warp * 3;
        lsum = v_pass<3>(hb, ww, lane, y0, oy + y0);
    } else {
        const int y0 = 18 + (warp - 6) * 2;
        lsum = v_pass<2>(hb, ww, lane, y0, oy + y0);
    }

    // --- block reduction -> double atomic + last-block finalize ---
#pragma unroll
    for (int o = 16; o; o >>= 1) lsum += __shfl_xor_sync(0xffffffffu, lsum, o);
    __shared__ float warp_part[8];
    if (lane == 0) warp_part[warp] = lsum;
    __syncthreads();
    if (tid == 0) {
        float v = 0.f;
#pragma unroll
        for (int i = 0; i < 8; i++) v += warp_part[i];
        atomicAdd(&g_acc, (double)v);
        __threadfence();
        unsigned int old = atomicAdd(&g_done, 1u);
        if (old == NBLOCKS - 1u) {
            __threadfence();
            double total = *((volatile double*)&g_acc);
            out[0] = 1.0f - (float)(total * (1.0 / NPIX));
            g_acc  = 0.0;
            g_done = 0u;
        }
    }
}

extern "C" void kernel_launch(void* const* d_in, const int* in_sizes, int n_in,
                              void* d_out, int out_size)
{
    const float* pred = (const float*)d_in[0];
    const float* targ = (const float*)d_in[1];
    const float* win  = (const float*)d_in[2];
    float* out = (float*)d_out;

    const int smem_bytes = 55808;
    cudaFuncSetAttribute(ssim_main_k, cudaFuncAttributeMaxDynamicSharedMemorySize, smem_bytes);

    dim3 grid(16, 24, 24), blk(256);
    ssim_main_k<<<grid, blk, smem_bytes>>>(pred, targ, win, out);
}